// round 3
// baseline (speedup 1.0000x reference)
#include <cuda_runtime.h>
#include <math.h>

#define FULLMASK 0xFFFFFFFFu

// ---------------- scratch (no allocations allowed) ----------------
__device__ double        g_acc[8];          // 0..2: ifd0..2, 3..4: scr0..1, 5: main
__device__ float         g_norm2[32 * 448]; // f0 @0 (32*64), f1 @2048 (32*128), f2 @6144 (32*256)
__device__ unsigned char g_flag [32 * 448]; // 0 = strong, 1 = weak
__device__ int           g_sel0[64];
__device__ int           g_sel1[128];

// ---------------- threefry2x32-20 (exact JAX semantics) ----------------
__device__ __forceinline__ void tf2x32(unsigned k0, unsigned k1,
                                       unsigned x0, unsigned x1,
                                       unsigned& o0, unsigned& o1) {
  unsigned ks2 = 0x1BD11BDAu ^ k0 ^ k1;
#define TFR(r) { x0 += x1; x1 = (x1 << (r)) | (x1 >> (32 - (r))); x1 ^= x0; }
  x0 += k0; x1 += k1;
  TFR(13) TFR(15) TFR(26) TFR(6)   x0 += k1;  x1 += ks2 + 1u;
  TFR(17) TFR(29) TFR(16) TFR(24)  x0 += ks2; x1 += k0 + 2u;
  TFR(13) TFR(15) TFR(26) TFR(6)   x0 += k0;  x1 += k1 + 3u;
  TFR(17) TFR(29) TFR(16) TFR(24)  x0 += k1;  x1 += ks2 + 4u;
  TFR(13) TFR(15) TFR(26) TFR(6)   x0 += ks2; x1 += k0 + 5u;
#undef TFR
  o0 = x0; o1 = x1;
}

// Reproduces: sel_key = key(42); for i in {0,1}:
//   ks, kt = split(fold_in(sel_key, i))           (kt = row 1)
//   key', subkey = split(kt)                       (subkey = row 1)
//   bits = threefry(subkey, iota(256))  [halves-split layout]
//   perm = stable-sort-carry(arange(256) by bits); sel_i = perm[:min_C]
__global__ void k_setup() {
  __shared__ unsigned keys[256];
  __shared__ int perm[256];
  int t = threadIdx.x;
  if (t < 8) g_acc[t] = 0.0;
#pragma unroll 1
  for (int i = 0; i < 2; i++) {
    unsigned kf0, kf1;
    tf2x32(0u, 42u, 0u, (unsigned)i, kf0, kf1);        // fold_in(key(42), i): count [0, i]
    unsigned a0, a1, b0, b1;
    tf2x32(kf0, kf1, 0u, 2u, a0, a1);                  // split: counts [0,1,2,3] -> lanes (0,2),(1,3)
    tf2x32(kf0, kf1, 1u, 3u, b0, b1);
    unsigned kt0 = a1, kt1 = b1;                       // kt = second split key
    unsigned c0, c1, d0, d1;
    tf2x32(kt0, kt1, 0u, 2u, c0, c1);                  // split(kt) inside _shuffle
    tf2x32(kt0, kt1, 1u, 3u, d0, d1);
    unsigned sk0 = c1, sk1 = d1;                       // subkey
    (void)a0; (void)b0; (void)c0; (void)d0;
    if (t < 128) {                                     // random bits: halves layout (j, j+128)
      unsigned y0, y1;
      tf2x32(sk0, sk1, (unsigned)t, (unsigned)(t + 128), y0, y1);
      keys[t] = y0; keys[t + 128] = y1;
    }
    __syncthreads();
    unsigned my = keys[t];
    int rank = 0;
    for (int j = 0; j < 256; j++) {                    // stable ascending sort rank
      unsigned kj = keys[j];
      rank += (kj < my) || (kj == my && j < t);
    }
    perm[rank] = t;
    __syncthreads();
    if (i == 0) { if (t <  64) g_sel0[t] = perm[t]; }
    else        { if (t < 128) g_sel1[t] = perm[t]; }
    __syncthreads();
  }
}

// ---------------- pass 1: per-(b,c) sum of squares ----------------
template <int HW, int TPB>
__global__ void k_norm(const float* __restrict__ x, int off) {
  int row = blockIdx.x;
  const float4* p = (const float4*)(x + (size_t)row * HW);
  float s = 0.f;
  for (int i = threadIdx.x; i < HW / 4; i += TPB) {
    float4 v = p[i];
    s += v.x * v.x + v.y * v.y + v.z * v.z + v.w * v.w;
  }
  __shared__ float sh[TPB / 32];
  for (int o = 16; o; o >>= 1) s += __shfl_down_sync(FULLMASK, s, o);
  if ((threadIdx.x & 31) == 0) sh[threadIdx.x >> 5] = s;
  __syncthreads();
  if (threadIdx.x == 0) {
    float tot = 0.f;
    for (int i = 0; i < TPB / 32; i++) tot += sh[i];
    g_norm2[off + row] = tot;
  }
}

// ---------------- channel ranking: strong = top C/2 by norm ----------------
__global__ void k_rank(int C, int off) {
  __shared__ float ns[256];
  int b = blockIdx.x, c = threadIdx.x;
  float v = g_norm2[off + b * C + c];
  ns[c] = v;
  __syncthreads();
  int rank = 0;
  for (int j = 0; j < C; j++) {
    float nj = ns[j];
    rank += (nj > v) || (nj == v && j < c);   // argsort(-norm), stable
  }
  g_flag[off + b * C + c] = (rank < C / 2) ? (unsigned char)0 : (unsigned char)1;
}

// ---------------- pass 2: IFD (+ fused SCR for students) ----------------
template <int C, int HW, int W, int SHIFT, int SEL_ID, int TPB, int VEC, int AI, int AS>
__global__ void k_ifd_scr(const float* __restrict__ x,
                          const float* __restrict__ teacher,
                          int flag_off) {
  constexpr bool HAS_T = (SEL_ID >= 0);
  constexpr int PIX = TPB * VEC;
  constexpr int BPB = HW / PIX;
  __shared__ unsigned char sflag[C];
  __shared__ int ssel[HAS_T ? C : 1];
  int b = blockIdx.x / BPB;
  int pb = blockIdx.x % BPB;
  int t = threadIdx.x;
  for (int c = t; c < C; c += TPB) {
    sflag[c] = g_flag[flag_off + b * C + c];
    if constexpr (HAS_T) ssel[c] = (SEL_ID == 0) ? g_sel0[c] : g_sel1[c];
  }
  __syncthreads();

  int p0 = pb * PIX + t * VEC;
  const float* xb = x + (size_t)b * C * HW + p0;
  float sS[VEC], sW[VEC];
#pragma unroll
  for (int j = 0; j < VEC; j++) { sS[j] = 0.f; sW[j] = 0.f; }
  float scr = 0.f;
  const float* tb = nullptr;
  int tpix = 0;
  if constexpr (HAS_T) {
    int h = p0 / W, w = p0 % W;
    tpix = (h >> SHIFT) * 32 + (w >> SHIFT);
    tb = teacher + (size_t)b * 256 * 1024;
  }

#pragma unroll 4
  for (int c = 0; c < C; c++) {
    float v[VEC];
    if constexpr (VEC == 4) {
      float4 q = *(const float4*)(xb + (size_t)c * HW);
      v[0] = q.x; v[1] = q.y; v[2] = q.z; v[3] = q.w;
    } else {
      v[0] = xb[(size_t)c * HW];
    }
    bool wk = (sflag[c] != 0);
#pragma unroll
    for (int j = 0; j < VEC; j++) {
      if (wk) sW[j] += v[j]; else sS[j] += v[j];
    }
    if constexpr (HAS_T) {
      const float* tc = tb + ssel[c] * 1024;
      if constexpr (SHIFT == 2) {              // feat0: 4 pixels -> 1 teacher texel
        float tv = tc[tpix];
#pragma unroll
        for (int j = 0; j < VEC; j++) { float d = v[j] - tv; scr += d * d; }
      } else {                                  // feat1: 4 pixels -> 2 teacher texels
        float2 tv = *(const float2*)(tc + tpix);
        float d0 = v[0] - tv.x, d1 = v[1] - tv.x, d2 = v[2] - tv.y, d3 = v[3] - tv.y;
        scr += d0 * d0 + d1 * d1 + d2 * d2 + d3 * d3;
      }
    }
  }

  float inv = 2.0f / (float)C;   // 1/half
  float ifd = 0.f;
#pragma unroll
  for (int j = 0; j < VEC; j++) {
    float aS = 1.f / (1.f + expf(-sS[j] * inv));
    float aW = 1.f / (1.f + expf(-sW[j] * inv));
    float d = aW - aS;
    ifd += d * d;
  }

  // block reduce in double, one atomic per block per quantity
  double di = (double)ifd, ds = (double)scr;
  for (int o = 16; o; o >>= 1) {
    di += __shfl_down_sync(FULLMASK, di, o);
    if constexpr (HAS_T) ds += __shfl_down_sync(FULLMASK, ds, o);
  }
  __shared__ double shd[2][TPB / 32];
  int wid = t >> 5;
  if ((t & 31) == 0) { shd[0][wid] = di; if constexpr (HAS_T) shd[1][wid] = ds; }
  __syncthreads();
  if (t == 0) {
    double ti = 0.0, ts = 0.0;
    for (int i = 0; i < TPB / 32; i++) { ti += shd[0][i]; if constexpr (HAS_T) ts += shd[1][i]; }
    atomicAdd(&g_acc[AI], ti);
    if constexpr (HAS_T) atomicAdd(&g_acc[AS], ts);
  }
}

// ---------------- l_main: log-softmax NLL ----------------
// NOTE: target is int32 on device (JAX x64-disabled downgrades jnp.int64).
__global__ void k_main(const float* __restrict__ pred, const int* __restrict__ tgt) {
  __shared__ float sh[8];
  __shared__ float shm;
  int b = blockIdx.x, t = threadIdx.x;
  const float* row = pred + b * 1000;
  float m = -1e30f;
  for (int i = t; i < 1000; i += 256) m = fmaxf(m, row[i]);
  for (int o = 16; o; o >>= 1) m = fmaxf(m, __shfl_down_sync(FULLMASK, m, o));
  if ((t & 31) == 0) sh[t >> 5] = m;
  __syncthreads();
  if (t == 0) {
    float mm = sh[0];
    for (int i = 1; i < 8; i++) mm = fmaxf(mm, sh[i]);
    shm = mm;
  }
  __syncthreads();
  m = shm;
  float s = 0.f;
  for (int i = t; i < 1000; i += 256) s += expf(row[i] - m);
  for (int o = 16; o; o >>= 1) s += __shfl_down_sync(FULLMASK, s, o);
  if ((t & 31) == 0) sh[t >> 5] = s;
  __syncthreads();
  if (t == 0) {
    float ss = 0.f;
    for (int i = 0; i < 8; i++) ss += sh[i];
    int tg = tgt[b];
    double lp = (double)(row[tg] - m) - log((double)ss);
    atomicAdd(&g_acc[5], -lp);
  }
}

// ---------------- finalize ----------------
__global__ void k_final(float* __restrict__ out) {
  double l_main = g_acc[5] / 32.0;
  double ifd0 = g_acc[0] / (32.0 * 128.0 * 128.0);
  double ifd1 = g_acc[1] / (32.0 * 64.0 * 64.0);
  double ifd2 = g_acc[2] / (32.0 * 32.0 * 32.0);
  double l_ifd = (ifd0 + ifd1 + ifd2) / 3.0;
  double scr0 = g_acc[3] / (32.0 * 64.0 * 128.0 * 128.0);
  double scr1 = g_acc[4] / (32.0 * 128.0 * 64.0 * 64.0);
  double l_scr = (scr0 + scr1) / 2.0;
  double total = l_main + 0.015 * l_scr + 0.015 * l_ifd;
  out[0] = (float)total;
  out[1] = (float)l_main;
  out[2] = (float)l_scr;
  out[3] = (float)l_ifd;
}

extern "C" void kernel_launch(void* const* d_in, const int* in_sizes, int n_in,
                              void* d_out, int out_size) {
  const float* pred = (const float*)d_in[0];
  const float* f0   = (const float*)d_in[1];   // (32, 64, 128, 128)
  const float* f1   = (const float*)d_in[2];   // (32, 128, 64, 64)
  const float* f2   = (const float*)d_in[3];   // (32, 256, 32, 32)
  const int*   tgt  = (const int*)d_in[4];     // int32 (JAX x64 disabled)
  float* out = (float*)d_out;

  k_setup<<<1, 256>>>();

  k_norm<16384, 256><<<32 * 64,  256>>>(f0, 0);
  k_norm< 4096, 256><<<32 * 128, 256>>>(f1, 2048);
  k_norm< 1024, 256><<<32 * 256, 256>>>(f2, 6144);

  k_rank<<<32,  64>>>(64,  0);
  k_rank<<<32, 128>>>(128, 2048);
  k_rank<<<32, 256>>>(256, 6144);

  // feat0: C=64, HW=16384, W=128, shift=2, sel0, 256 thr x vec4 -> 512 blocks
  k_ifd_scr< 64, 16384, 128, 2,  0, 256, 4, 0, 3><<<512, 256>>>(f0, f2, 0);
  // feat1: C=128, HW=4096, W=64, shift=1, sel1, 64 thr x vec4 -> 512 blocks
  k_ifd_scr<128,  4096,  64, 1,  1,  64, 4, 1, 4><<<512,  64>>>(f1, f2, 2048);
  // feat2: C=256, HW=1024, W=32, no teacher, 128 thr x vec1 -> 256 blocks
  k_ifd_scr<256,  1024,  32, 0, -1, 128, 1, 2, 6><<<256, 128>>>(f2, nullptr, 6144);

  k_main<<<32, 256>>>(pred, tgt);
  k_final<<<1, 1>>>(out);
}

// round 4
// speedup vs baseline: 2.2723x; 2.2723x over previous
#include <cuda_runtime.h>
#include <math.h>

#define FULLMASK 0xFFFFFFFFu

// ---------------- scratch (no allocations allowed) ----------------
__device__ double g_acc[8];           // 0..2: ifd0..2, 3..4: scr0..1
__device__ double g_main_part[32];    // per-batch -logp
__device__ float  g_norm2[32 * 448];  // f0 @0 (32*64), f1 @2048 (32*128), f2 @6144 (32*256)
__device__ int    g_sel0[64];
__device__ int    g_sel1[128];

// ---------------- threefry2x32-20 (exact JAX semantics) ----------------
__device__ __forceinline__ void tf2x32(unsigned k0, unsigned k1,
                                       unsigned x0, unsigned x1,
                                       unsigned& o0, unsigned& o1) {
  unsigned ks2 = 0x1BD11BDAu ^ k0 ^ k1;
#define TFR(r) { x0 += x1; x1 = (x1 << (r)) | (x1 >> (32 - (r))); x1 ^= x0; }
  x0 += k0; x1 += k1;
  TFR(13) TFR(15) TFR(26) TFR(6)   x0 += k1;  x1 += ks2 + 1u;
  TFR(17) TFR(29) TFR(16) TFR(24)  x0 += ks2; x1 += k0 + 2u;
  TFR(13) TFR(15) TFR(26) TFR(6)   x0 += k0;  x1 += k1 + 3u;
  TFR(17) TFR(29) TFR(16) TFR(24)  x0 += k1;  x1 += ks2 + 4u;
  TFR(13) TFR(15) TFR(26) TFR(6)   x0 += ks2; x1 += k0 + 5u;
#undef TFR
  o0 = x0; o1 = x1;
}

// sel_key = key(42); for i in {0,1}: ks,kt = split(fold_in(sel_key,i));
// subkey = split(kt)[1]; bits = threefry(subkey, iota(256)) halves layout;
// perm = stable argsort; sel_i = perm[:min_C]
__device__ void setup_body() {
  __shared__ unsigned keys[256];
  __shared__ int perm[256];
  int t = threadIdx.x;
  if (t < 8) g_acc[t] = 0.0;
#pragma unroll 1
  for (int i = 0; i < 2; i++) {
    unsigned kf0, kf1;
    tf2x32(0u, 42u, 0u, (unsigned)i, kf0, kf1);
    unsigned a0, a1, b0, b1;
    tf2x32(kf0, kf1, 0u, 2u, a0, a1);
    tf2x32(kf0, kf1, 1u, 3u, b0, b1);
    unsigned kt0 = a1, kt1 = b1;
    unsigned c0, c1, d0, d1;
    tf2x32(kt0, kt1, 0u, 2u, c0, c1);
    tf2x32(kt0, kt1, 1u, 3u, d0, d1);
    unsigned sk0 = c1, sk1 = d1;
    (void)a0; (void)b0; (void)c0; (void)d0;
    if (t < 128) {
      unsigned y0, y1;
      tf2x32(sk0, sk1, (unsigned)t, (unsigned)(t + 128), y0, y1);
      keys[t] = y0; keys[t + 128] = y1;
    }
    __syncthreads();
    unsigned my = keys[t];
    int rank = 0;
    for (int j = 0; j < 256; j++) {
      unsigned kj = keys[j];
      rank += (kj < my) || (kj == my && j < t);
    }
    perm[rank] = t;
    __syncthreads();
    if (i == 0) { if (t <  64) g_sel0[t] = perm[t]; }
    else        { if (t < 128) g_sel1[t] = perm[t]; }
    __syncthreads();
  }
}

// ---------------- norms: warp per row, 8 rows per block ----------------
template <int HW>
__device__ __forceinline__ void norm_rows(const float* __restrict__ x, int row0, int off) {
  int w = threadIdx.x >> 5, lane = threadIdx.x & 31;
  int row = row0 + w;
  const float4* p = (const float4*)(x + (size_t)row * HW);
  float s = 0.f;
#pragma unroll 4
  for (int i = lane; i < HW / 4; i += 32) {
    float4 v = p[i];
    s += v.x * v.x + v.y * v.y + v.z * v.z + v.w * v.w;
  }
  for (int o = 16; o; o >>= 1) s += __shfl_down_sync(FULLMASK, s, o);
  if (lane == 0) g_norm2[off + row] = s;
}

// ---------------- l_main body: one block per batch ----------------
__device__ void main_body(const float* __restrict__ pred, const int* __restrict__ tgt, int b) {
  __shared__ float sh[8];
  __shared__ float shm;
  int t = threadIdx.x;
  const float* row = pred + b * 1000;
  float m = -1e30f;
  for (int i = t; i < 1000; i += 256) m = fmaxf(m, row[i]);
  for (int o = 16; o; o >>= 1) m = fmaxf(m, __shfl_down_sync(FULLMASK, m, o));
  if ((t & 31) == 0) sh[t >> 5] = m;
  __syncthreads();
  if (t == 0) {
    float mm = sh[0];
    for (int i = 1; i < 8; i++) mm = fmaxf(mm, sh[i]);
    shm = mm;
  }
  __syncthreads();
  m = shm;
  float s = 0.f;
  for (int i = t; i < 1000; i += 256) s += expf(row[i] - m);
  for (int o = 16; o; o >>= 1) s += __shfl_down_sync(FULLMASK, s, o);
  if ((t & 31) == 0) sh[t >> 5] = s;
  __syncthreads();
  if (t == 0) {
    float ss = 0.f;
    for (int i = 0; i < 8; i++) ss += sh[i];
    int tg = tgt[b];
    double lp = (double)(row[tg] - m) - log((double)ss);
    g_main_part[b] = -lp;
  }
}

// ---------------- kernel A: setup + norms + l_main ----------------
__global__ void k_passA(const float* __restrict__ pred,
                        const float* __restrict__ f0,
                        const float* __restrict__ f1,
                        const float* __restrict__ f2,
                        const int* __restrict__ tgt) {
  int bid = blockIdx.x;
  if      (bid <  256) norm_rows<16384>(f0, bid * 8, 0);             // 2048 rows
  else if (bid <  768) norm_rows< 4096>(f1, (bid -  256) * 8, 2048); // 4096 rows
  else if (bid < 1792) norm_rows< 1024>(f2, (bid -  768) * 8, 6144); // 8192 rows
  else if (bid < 1824) main_body(pred, tgt, bid - 1792);
  else                 setup_body();
}

// ---------------- pass 2 body: inline rank + IFD (+ fused SCR) ----------------
// TPB fixed at 256. VEC pixels per thread; teacher texel shared by the VEC group.
template <int C, int HW, int W, int SHIFT, int SEL_ID, int VEC, int AI, int AS>
__device__ void ifd_body(const float* __restrict__ x,
                         const float* __restrict__ teacher,
                         int off, int blk) {
  constexpr bool HAS_T = (SEL_ID >= 0);
  constexpr int TPB = 256;
  constexpr int PIX = TPB * VEC;
  constexpr int BPB = HW / PIX;
  __shared__ float ns[C];
  __shared__ unsigned char sflag[C];
  __shared__ int ssel[HAS_T ? C : 1];
  __shared__ double shd[2][TPB / 32];

  int b = blk / BPB;
  int pb = blk % BPB;
  int t = threadIdx.x;

  if (t < C) ns[t] = g_norm2[off + b * C + t];
  if constexpr (HAS_T) {
    if (t < C) ssel[t] = (SEL_ID == 0) ? g_sel0[t] : g_sel1[t];
  }
  __syncthreads();
  if (t < C) {
    float v = ns[t];
    int rank = 0;
#pragma unroll 4
    for (int j = 0; j < C; j++) {
      float nj = ns[j];
      rank += (nj > v) || (nj == v && j < t);   // argsort(-norm), stable
    }
    sflag[t] = (rank < C / 2) ? (unsigned char)0 : (unsigned char)1;
  }
  __syncthreads();

  int p0 = pb * PIX + t * VEC;
  const float* xb = x + (size_t)b * C * HW + p0;
  float sS[VEC], sW[VEC];
#pragma unroll
  for (int j = 0; j < VEC; j++) { sS[j] = 0.f; sW[j] = 0.f; }
  float scr = 0.f;
  const float* tb = nullptr;
  int tpix = 0;
  if constexpr (HAS_T) {
    int h = p0 / W, w = p0 % W;
    tpix = (h >> SHIFT) * 32 + (w >> SHIFT);
    tb = teacher + (size_t)b * 256 * 1024;
  }

#pragma unroll 4
  for (int c = 0; c < C; c++) {
    float v[VEC];
    if constexpr (VEC == 4) {
      float4 q = *(const float4*)(xb + (size_t)c * HW);
      v[0] = q.x; v[1] = q.y; v[2] = q.z; v[3] = q.w;
    } else if constexpr (VEC == 2) {
      float2 q = *(const float2*)(xb + (size_t)c * HW);
      v[0] = q.x; v[1] = q.y;
    } else {
      v[0] = xb[(size_t)c * HW];
    }
    bool wk = (sflag[c] != 0);
#pragma unroll
    for (int j = 0; j < VEC; j++) {
      if (wk) sW[j] += v[j]; else sS[j] += v[j];
    }
    if constexpr (HAS_T) {
      float tv = tb[ssel[c] * 1024 + tpix];   // one texel covers the whole VEC group
#pragma unroll
      for (int j = 0; j < VEC; j++) { float d = v[j] - tv; scr += d * d; }
    }
  }

  float inv = 2.0f / (float)C;   // 1/half
  float ifd = 0.f;
#pragma unroll
  for (int j = 0; j < VEC; j++) {
    float aS = 1.f / (1.f + expf(-sS[j] * inv));
    float aW = 1.f / (1.f + expf(-sW[j] * inv));
    float d = aW - aS;
    ifd += d * d;
  }

  double di = (double)ifd, ds = (double)scr;
  for (int o = 16; o; o >>= 1) {
    di += __shfl_down_sync(FULLMASK, di, o);
    if constexpr (HAS_T) ds += __shfl_down_sync(FULLMASK, ds, o);
  }
  int wid = t >> 5;
  if ((t & 31) == 0) { shd[0][wid] = di; if constexpr (HAS_T) shd[1][wid] = ds; }
  __syncthreads();
  if (t == 0) {
    double ti = 0.0, ts = 0.0;
    for (int i = 0; i < TPB / 32; i++) { ti += shd[0][i]; if constexpr (HAS_T) ts += shd[1][i]; }
    atomicAdd(&g_acc[AI], ti);
    if constexpr (HAS_T) atomicAdd(&g_acc[AS], ts);
  }
}

// ---------------- kernel B: all pass-2 work in one launch ----------------
__global__ void k_passB(const float* __restrict__ f0,
                        const float* __restrict__ f1,
                        const float* __restrict__ f2) {
  int bid = blockIdx.x;
  if (bid < 512)      ifd_body< 64, 16384, 128, 2,  0, 4, 0, 3>(f0, f2, 0,    bid);        // 32*16
  else if (bid < 768) ifd_body<128,  4096,  64, 1,  1, 2, 1, 4>(f1, f2, 2048, bid - 512);  // 32*8
  else                ifd_body<256,  1024,  32, 0, -1, 1, 2, 6>(f2, nullptr, 6144, bid - 768); // 32*4
}

// ---------------- finalize ----------------
__global__ void k_final(float* __restrict__ out) {
  double lm = 0.0;
  for (int i = 0; i < 32; i++) lm += g_main_part[i];
  double l_main = lm / 32.0;
  double ifd0 = g_acc[0] / (32.0 * 128.0 * 128.0);
  double ifd1 = g_acc[1] / (32.0 * 64.0 * 64.0);
  double ifd2 = g_acc[2] / (32.0 * 32.0 * 32.0);
  double l_ifd = (ifd0 + ifd1 + ifd2) / 3.0;
  double scr0 = g_acc[3] / (32.0 * 64.0 * 128.0 * 128.0);
  double scr1 = g_acc[4] / (32.0 * 128.0 * 64.0 * 64.0);
  double l_scr = (scr0 + scr1) / 2.0;
  double total = l_main + 0.015 * l_scr + 0.015 * l_ifd;
  out[0] = (float)total;
  out[1] = (float)l_main;
  out[2] = (float)l_scr;
  out[3] = (float)l_ifd;
}

extern "C" void kernel_launch(void* const* d_in, const int* in_sizes, int n_in,
                              void* d_out, int out_size) {
  const float* pred = (const float*)d_in[0];
  const float* f0   = (const float*)d_in[1];   // (32, 64, 128, 128)
  const float* f1   = (const float*)d_in[2];   // (32, 128, 64, 64)
  const float* f2   = (const float*)d_in[3];   // (32, 256, 32, 32)
  const int*   tgt  = (const int*)d_in[4];     // int32 (JAX x64 disabled)
  float* out = (float*)d_out;

  k_passA<<<1825, 256>>>(pred, f0, f1, f2, tgt);
  k_passB<<<896, 256>>>(f0, f1, f2);
  k_final<<<1, 1>>>(out);
}